// round 4
// baseline (speedup 1.0000x reference)
#include <cuda_runtime.h>
#include <cuda_bf16.h>

#define NN 100000
#define EE 3200000
#define IND 128
#define HD 64
#define OD 2

// Scratch (static __device__ arrays per allocation rules)
__device__ float g_dinv[NN];                     // 0.4 MB  (degree, then rsqrt(degree))
__device__ float g_h1[(size_t)NN * HD];          // 25.6 MB (x @ W1)
__device__ float g_out1[(size_t)NN * HD];        // 25.6 MB (aggregated layer-1 output, pre-relu)
__device__ float g_h2[(size_t)NN * OD];          // 0.8 MB  (relu(out1) @ W2)

// ---------------- degree / normalization ----------------

__global__ void k_deg_init(int n) {
    int i = blockIdx.x * blockDim.x + threadIdx.x;
    if (i < n) g_dinv[i] = 1.0f;   // self-loop contributes 1 to in-degree
}

__global__ void k_deg_count(const int* __restrict__ ei, int e) {
    int stride = gridDim.x * blockDim.x;
    for (int i = blockIdx.x * blockDim.x + threadIdx.x; i < e; i += stride) {
        int dst = ei[(size_t)e + i];
        atomicAdd(&g_dinv[dst], 1.0f);
    }
}

__global__ void k_dinv(int n) {
    int i = blockIdx.x * blockDim.x + threadIdx.x;
    if (i < n) g_dinv[i] = rsqrtf(g_dinv[i]);    // deg >= 1 always (self-loop)
}

// ---------------- layer 1 GEMM: h1 = x @ W1 ; out1 = h1*dinv^2 + b1 ----------------
// Persistent blocks, W1 (128x64 = 32KB) staged in shared once per block.
// 256 threads = 8 warps; each tile = 8 rows; warp w computes row w, lane handles 2 cols.

__global__ void __launch_bounds__(256) k_gemm1(const float* __restrict__ x,
                                               const float* __restrict__ W1,
                                               const float* __restrict__ b1, int n) {
    __shared__ float Ws[IND * HD];   // 32 KB
    __shared__ float xs[8][IND];     // 4 KB
    for (int i = threadIdx.x; i < IND * HD; i += blockDim.x) Ws[i] = W1[i];
    __syncthreads();

    int warp = threadIdx.x >> 5;
    int lane = threadIdx.x & 31;
    int ntiles = (n + 7) / 8;

    for (int t = blockIdx.x; t < ntiles; t += gridDim.x) {
        int rowBase = t * 8;
        // cooperative load of 8 x-rows (1024 floats) via one float4 per thread
        {
            int r = threadIdx.x >> 5;           // 0..7
            int c = (threadIdx.x & 31) * 4;     // 0..124
            int row = rowBase + r;
            float4 v = make_float4(0.f, 0.f, 0.f, 0.f);
            if (row < n) v = *(const float4*)&x[(size_t)row * IND + c];
            *(float4*)&xs[r][c] = v;
        }
        __syncthreads();

        int row = rowBase + warp;
        if (row < n) {
            float a0 = 0.f, a1 = 0.f;
            int c = lane * 2;
            #pragma unroll 16
            for (int k = 0; k < IND; k++) {
                float xv = xs[warp][k];                       // warp broadcast
                float2 w = *(const float2*)&Ws[k * HD + c];   // conflict-free
                a0 += xv * w.x;
                a1 += xv * w.y;
            }
            float d = g_dinv[row];
            float dd = d * d;
            size_t o = (size_t)row * HD + c;
            g_h1[o]     = a0;
            g_h1[o + 1] = a1;
            g_out1[o]     = a0 * dd + b1[c];       // self-loop term + bias, no zero pass
            g_out1[o + 1] = a1 * dd + b1[c + 1];
        }
        __syncthreads();
    }
}

// ---------------- layer 1 scatter: out1[dst] += h1[src] * dinv[src]*dinv[dst] ----------------
// One warp per edge; lane covers 2 contiguous columns (float2 gather + 2 RED.ADD.F32).

__global__ void __launch_bounds__(256) k_scatter1(const int* __restrict__ ei, int e) {
    int lane = threadIdx.x & 31;
    int warpId = (blockIdx.x * blockDim.x + threadIdx.x) >> 5;
    int nwarps = (gridDim.x * blockDim.x) >> 5;
    for (int i = warpId; i < e; i += nwarps) {
        int sd = 0;
        if (lane < 2) sd = ei[(size_t)lane * e + i];
        int src = __shfl_sync(0xffffffffu, sd, 0);
        int dst = __shfl_sync(0xffffffffu, sd, 1);
        float norm = g_dinv[src] * g_dinv[dst];
        const float2 v = *(const float2*)&g_h1[(size_t)src * HD + lane * 2];
        float* o = &g_out1[(size_t)dst * HD + lane * 2];
        atomicAdd(o,     v.x * norm);
        atomicAdd(o + 1, v.y * norm);
    }
}

// ---------------- layer 2 GEMM: h2 = relu(out1) @ W2 ; out = h2*dinv^2 + b2 ----------------

__global__ void __launch_bounds__(256) k_gemm2(const float* __restrict__ W2,
                                               const float* __restrict__ b2,
                                               float* __restrict__ out, int n) {
    __shared__ float Ws[HD * OD];   // 512 B, [k][2] layout
    __shared__ float bs[OD];
    for (int i = threadIdx.x; i < HD * OD; i += blockDim.x) Ws[i] = W2[i];
    if (threadIdx.x < OD) bs[threadIdx.x] = b2[threadIdx.x];
    __syncthreads();

    int i = blockIdx.x * blockDim.x + threadIdx.x;
    if (i >= n) return;
    float a0 = 0.f, a1 = 0.f;
    const float* h = &g_out1[(size_t)i * HD];
    #pragma unroll
    for (int k = 0; k < HD; k += 4) {
        float4 v = *(const float4*)&h[k];
        v.x = fmaxf(v.x, 0.f);
        v.y = fmaxf(v.y, 0.f);
        v.z = fmaxf(v.z, 0.f);
        v.w = fmaxf(v.w, 0.f);
        a0 += v.x * Ws[(k + 0) * 2] + v.y * Ws[(k + 1) * 2]
            + v.z * Ws[(k + 2) * 2] + v.w * Ws[(k + 3) * 2];
        a1 += v.x * Ws[(k + 0) * 2 + 1] + v.y * Ws[(k + 1) * 2 + 1]
            + v.z * Ws[(k + 2) * 2 + 1] + v.w * Ws[(k + 3) * 2 + 1];
    }
    g_h2[(size_t)i * 2]     = a0;
    g_h2[(size_t)i * 2 + 1] = a1;
    float d = g_dinv[i];
    float dd = d * d;
    out[(size_t)i * 2]     = a0 * dd + bs[0];   // self-loop + bias init (overwrites poison)
    out[(size_t)i * 2 + 1] = a1 * dd + bs[1];
}

// ---------------- layer 2 scatter: out[dst] += h2[src] * norm ----------------

__global__ void __launch_bounds__(256) k_scatter2(const int* __restrict__ ei,
                                                  float* __restrict__ out, int e) {
    int stride = gridDim.x * blockDim.x;
    for (int i = blockIdx.x * blockDim.x + threadIdx.x; i < e; i += stride) {
        int src = ei[i];
        int dst = ei[(size_t)e + i];
        float norm = g_dinv[src] * g_dinv[dst];
        float2 v = *(const float2*)&g_h2[(size_t)src * 2];
        atomicAdd(&out[(size_t)dst * 2],     v.x * norm);
        atomicAdd(&out[(size_t)dst * 2 + 1], v.y * norm);
    }
}

// ---------------- launch ----------------

extern "C" void kernel_launch(void* const* d_in, const int* in_sizes, int n_in,
                              void* d_out, int out_size) {
    const float* x  = (const float*)d_in[0];
    const int*   ei = (const int*)d_in[1];       // JAX default x64-disabled: int32
    const float* W1 = (const float*)d_in[2];
    const float* b1 = (const float*)d_in[3];
    const float* W2 = (const float*)d_in[4];
    const float* b2 = (const float*)d_in[5];
    float* out = (float*)d_out;

    int n = in_sizes[0] / IND;   // 100000
    int e = in_sizes[1] / 2;     // 3200000

    k_deg_init <<<(n + 255) / 256, 256>>>(n);
    k_deg_count<<<2048, 256>>>(ei, e);
    k_dinv     <<<(n + 255) / 256, 256>>>(n);
    k_gemm1    <<<888, 256>>>(x, W1, b1, n);
    k_scatter1 <<<4096, 256>>>(ei, e);
    k_gemm2    <<<(n + 255) / 256, 256>>>(W2, b2, out, n);
    k_scatter2 <<<2048, 256>>>(ei, out, e);
}

// round 5
// speedup vs baseline: 2.0110x; 2.0110x over previous
#include <cuda_runtime.h>
#include <cuda_bf16.h>

#define NN 100000
#define EE 3200000
#define IND 128
#define HD 64
#define OD 2

// ---- scratch (__device__ globals per allocation rules) ----
__device__ int   g_cnt[NN];                 // in-degree (excl. self-loop)
__device__ float g_dinv[NN];                // rsqrt(deg+1)
__device__ int   g_pexcl[NN];               // per-block exclusive scan partials
__device__ int   g_bsum[256];               // block sums
__device__ int   g_boff[256];               // block offsets
__device__ int   g_rowstart[NN + 1];        // CSR row offsets (by dst)
__device__ int   g_cursor[NN];              // fill cursors
__device__ int   g_csr[EE];                 // CSR payload: src node ids
__device__ float g_h1s[(size_t)NN * HD];    // dinv[r] * (x @ W1)[r]
__device__ float g_a1[(size_t)NN * HD];     // relu(layer1 out)
__device__ float g_h2s[(size_t)NN * OD];    // dinv[r] * (a1 @ W2)[r]

// ---------------- histogram / normalization ----------------

__global__ void k_zero(int n) {
    int i = blockIdx.x * blockDim.x + threadIdx.x;
    if (i < n) g_cnt[i] = 0;
}

__global__ void k_hist(const int* __restrict__ ei, int e) {
    int stride = gridDim.x * blockDim.x;
    for (int i = blockIdx.x * blockDim.x + threadIdx.x; i < e; i += stride)
        atomicAdd(&g_cnt[ei[(size_t)e + i]], 1);
}

__global__ void k_dinv(int n) {
    int i = blockIdx.x * blockDim.x + threadIdx.x;
    if (i < n) g_dinv[i] = rsqrtf((float)g_cnt[i] + 1.0f);
}

// ---------------- 2-level exclusive scan (512 elems / block) ----------------

__global__ void __launch_bounds__(256) k_scan_local(int n) {
    __shared__ int wtot[8];
    int t = threadIdx.x, lane = t & 31, warp = t >> 5;
    int base = blockIdx.x * 512;
    int i0 = base + 2 * t;
    int a = (i0 < n) ? g_cnt[i0] : 0;
    int b = (i0 + 1 < n) ? g_cnt[i0 + 1] : 0;
    int tsum = a + b;
    int incl = tsum;
    #pragma unroll
    for (int o = 1; o < 32; o <<= 1) {
        int v = __shfl_up_sync(0xffffffffu, incl, o);
        if (lane >= o) incl += v;
    }
    if (lane == 31) wtot[warp] = incl;
    __syncthreads();
    if (t < 8) {
        int v = wtot[t], s = v;
        #pragma unroll
        for (int o = 1; o < 8; o <<= 1) {
            int u = __shfl_up_sync(0xffu, s, o);
            if (t >= o) s += u;
        }
        wtot[t] = s;
    }
    __syncthreads();
    int pref = (warp > 0 ? wtot[warp - 1] : 0);
    int excl = incl + pref - tsum;      // exclusive prefix at element 2t
    if (i0 < n)     g_pexcl[i0] = excl;
    if (i0 + 1 < n) g_pexcl[i0 + 1] = excl + a;
    if (t == 255) g_bsum[blockIdx.x] = wtot[7];
}

__global__ void __launch_bounds__(256) k_scan_block(int nblk) {
    __shared__ int wtot[8];
    int t = threadIdx.x, lane = t & 31, warp = t >> 5;
    int v = (t < nblk) ? g_bsum[t] : 0;
    int incl = v;
    #pragma unroll
    for (int o = 1; o < 32; o <<= 1) {
        int u = __shfl_up_sync(0xffffffffu, incl, o);
        if (lane >= o) incl += u;
    }
    if (lane == 31) wtot[warp] = incl;
    __syncthreads();
    if (t < 8) {
        int x = wtot[t], s = x;
        #pragma unroll
        for (int o = 1; o < 8; o <<= 1) {
            int u = __shfl_up_sync(0xffu, s, o);
            if (t >= o) s += u;
        }
        wtot[t] = s;
    }
    __syncthreads();
    int pref = (warp > 0 ? wtot[warp - 1] : 0);
    if (t < nblk) g_boff[t] = incl + pref - v;   // exclusive
}

__global__ void k_scan_add(int n, int e) {
    int i = blockIdx.x * blockDim.x + threadIdx.x;
    if (i < n) {
        int off = g_pexcl[i] + g_boff[i >> 9];
        g_rowstart[i] = off;
        g_cursor[i]   = off;
    }
    if (i == 0) g_rowstart[n] = e;
}

__global__ void k_fill(const int* __restrict__ ei, int e) {
    int stride = gridDim.x * blockDim.x;
    for (int i = blockIdx.x * blockDim.x + threadIdx.x; i < e; i += stride) {
        int src = ei[i];
        int dst = ei[(size_t)e + i];
        int p = atomicAdd(&g_cursor[dst], 1);
        g_csr[p] = src;
    }
}

// ---------------- gemm1: g_h1s[r] = dinv[r] * (x[r] @ W1) ----------------
// Persistent, 32-row tiles. Thread = 2 rows x 4 cols (8 acc). x staged k-major.

__global__ void __launch_bounds__(256) k_gemm1(const float* __restrict__ x,
                                               const float* __restrict__ W1, int n) {
    __shared__ float Ws[IND * HD];     // 32 KB
    __shared__ float xsT[IND * 32];    // 16 KB, k-major: xsT[k*32 + r]
    int t = threadIdx.x;
    for (int i = t; i < IND * HD; i += 256) Ws[i] = W1[i];

    int r0 = (t >> 4) * 2;             // 0,2,..,30
    int r1 = r0 + 1;
    int c4 = (t & 15) * 4;             // 0..60
    int ntiles = (n + 31) / 32;

    for (int tile = blockIdx.x; tile < ntiles; tile += gridDim.x) {
        int rowBase = tile * 32;
        __syncthreads();
        // load 32x128 x-tile transposed; lane-stride-1 smem stores (conflict-free)
        for (int i = t; i < 1024; i += 256) {
            int row = i & 31;
            int cc  = (i >> 5) * 4;
            float4 v = make_float4(0.f, 0.f, 0.f, 0.f);
            if (rowBase + row < n)
                v = *(const float4*)&x[(size_t)(rowBase + row) * IND + cc];
            xsT[(cc + 0) * 32 + row] = v.x;
            xsT[(cc + 1) * 32 + row] = v.y;
            xsT[(cc + 2) * 32 + row] = v.z;
            xsT[(cc + 3) * 32 + row] = v.w;
        }
        __syncthreads();

        float a00 = 0.f, a01 = 0.f, a02 = 0.f, a03 = 0.f;
        float a10 = 0.f, a11 = 0.f, a12 = 0.f, a13 = 0.f;
        #pragma unroll 16
        for (int k = 0; k < IND; k++) {
            float4 w = *(const float4*)&Ws[k * HD + c4];
            float x0 = xsT[k * 32 + r0];
            float x1 = xsT[k * 32 + r1];
            a00 += x0 * w.x; a01 += x0 * w.y; a02 += x0 * w.z; a03 += x0 * w.w;
            a10 += x1 * w.x; a11 += x1 * w.y; a12 += x1 * w.z; a13 += x1 * w.w;
        }
        int row0 = rowBase + r0, row1 = rowBase + r1;
        if (row0 < n) {
            float d = g_dinv[row0];
            *(float4*)&g_h1s[(size_t)row0 * HD + c4] =
                make_float4(a00 * d, a01 * d, a02 * d, a03 * d);
        }
        if (row1 < n) {
            float d = g_dinv[row1];
            *(float4*)&g_h1s[(size_t)row1 * HD + c4] =
                make_float4(a10 * d, a11 * d, a12 * d, a13 * d);
        }
    }
}

// ---------------- gather1: a1[dst] = relu(dinv[dst]*(sum h1s[src] + h1s[dst]) + b1) ----------------
// Warp per dst row; lane covers 2 cols (float2). 32-edge batches via shuffle.

__global__ void __launch_bounds__(256) k_gather1(const float* __restrict__ b1, int n) {
    int lane = threadIdx.x & 31;
    int row = blockIdx.x * 8 + (threadIdx.x >> 5);
    if (row >= n) return;
    int start = g_rowstart[row];
    int end   = g_rowstart[row + 1];
    int c = lane * 2;

    float2 acc = *(const float2*)&g_h1s[(size_t)row * HD + c];  // self term
    int j = start;
    while (j + 32 <= end) {
        int idx = g_csr[j + lane];
        #pragma unroll 8
        for (int k = 0; k < 32; k++) {
            int s = __shfl_sync(0xffffffffu, idx, k);
            float2 v = *(const float2*)&g_h1s[(size_t)s * HD + c];
            acc.x += v.x; acc.y += v.y;
        }
        j += 32;
    }
    if (j < end) {
        int m = end - j;
        int idx = (lane < m) ? g_csr[j + lane] : 0;
        for (int k = 0; k < m; k++) {
            int s = __shfl_sync(0xffffffffu, idx, k);
            float2 v = *(const float2*)&g_h1s[(size_t)s * HD + c];
            acc.x += v.x; acc.y += v.y;
        }
    }
    float d = g_dinv[row];
    float r0 = fmaxf(acc.x * d + b1[c], 0.f);
    float r1 = fmaxf(acc.y * d + b1[c + 1], 0.f);
    *(float2*)&g_a1[(size_t)row * HD + c] = make_float2(r0, r1);
}

// ---------------- gemm2: g_h2s[r] = dinv[r] * (a1[r] @ W2) ----------------

__global__ void __launch_bounds__(256) k_gemm2(const float* __restrict__ W2, int n) {
    __shared__ float Ws[HD * OD];
    for (int i = threadIdx.x; i < HD * OD; i += blockDim.x) Ws[i] = W2[i];
    __syncthreads();
    int i = blockIdx.x * blockDim.x + threadIdx.x;
    if (i >= n) return;
    float a0 = 0.f, a1 = 0.f;
    const float* h = &g_a1[(size_t)i * HD];
    #pragma unroll
    for (int k = 0; k < HD; k += 4) {
        float4 v = *(const float4*)&h[k];
        a0 += v.x * Ws[(k + 0) * 2]     + v.y * Ws[(k + 1) * 2]
            + v.z * Ws[(k + 2) * 2]     + v.w * Ws[(k + 3) * 2];
        a1 += v.x * Ws[(k + 0) * 2 + 1] + v.y * Ws[(k + 1) * 2 + 1]
            + v.z * Ws[(k + 2) * 2 + 1] + v.w * Ws[(k + 3) * 2 + 1];
    }
    float d = g_dinv[i];
    *(float2*)&g_h2s[(size_t)i * OD] = make_float2(a0 * d, a1 * d);
}

// ---------------- gather2: out[dst] = dinv[dst]*(sum h2s[src] + h2s[dst]) + b2 ----------------
// Warp per dst row; lanes parallel over edges; butterfly reduce.

__global__ void __launch_bounds__(256) k_gather2(const float* __restrict__ b2,
                                                 float* __restrict__ out, int n) {
    int lane = threadIdx.x & 31;
    int row = blockIdx.x * 8 + (threadIdx.x >> 5);
    if (row >= n) return;
    int start = g_rowstart[row];
    int end   = g_rowstart[row + 1];

    float2 acc = make_float2(0.f, 0.f);
    for (int j = start + lane; j < end; j += 32) {
        int s = g_csr[j];
        float2 v = *(const float2*)&g_h2s[(size_t)s * OD];
        acc.x += v.x; acc.y += v.y;
    }
    #pragma unroll
    for (int o = 16; o > 0; o >>= 1) {
        acc.x += __shfl_xor_sync(0xffffffffu, acc.x, o);
        acc.y += __shfl_xor_sync(0xffffffffu, acc.y, o);
    }
    if (lane == 0) {
        float2 self = *(const float2*)&g_h2s[(size_t)row * OD];
        float d = g_dinv[row];
        *(float2*)&out[(size_t)row * OD] =
            make_float2((acc.x + self.x) * d + b2[0],
                        (acc.y + self.y) * d + b2[1]);
    }
}

// ---------------- launch ----------------

extern "C" void kernel_launch(void* const* d_in, const int* in_sizes, int n_in,
                              void* d_out, int out_size) {
    const float* x  = (const float*)d_in[0];
    const int*   ei = (const int*)d_in[1];       // int32 (JAX x64 disabled)
    const float* W1 = (const float*)d_in[2];
    const float* b1 = (const float*)d_in[3];
    const float* W2 = (const float*)d_in[4];
    const float* b2 = (const float*)d_in[5];
    float* out = (float*)d_out;

    int n = in_sizes[0] / IND;    // 100000
    int e = in_sizes[1] / 2;      // 3200000
    int nblk = (n + 511) / 512;   // 196

    int nb256 = (n + 255) / 256;
    k_zero      <<<nb256, 256>>>(n);
    k_hist      <<<2048, 256>>>(ei, e);
    k_dinv      <<<nb256, 256>>>(n);
    k_scan_local<<<nblk, 256>>>(n);
    k_scan_block<<<1, 256>>>(nblk);
    k_scan_add  <<<nb256, 256>>>(n, e);
    k_fill      <<<2048, 256>>>(ei, e);
    k_gemm1     <<<592, 256>>>(x, W1, n);
    k_gather1   <<<(n + 7) / 8, 256>>>(b1, n);
    k_gemm2     <<<nb256, 256>>>(W2, n);
    k_gather2   <<<(n + 7) / 8, 256>>>(b2, out, n);
}